// round 2
// baseline (speedup 1.0000x reference)
#include <cuda_runtime.h>
#include <math.h>

#define B_   256
#define T_   256
#define IN_  256
#define HID_ 512
#define OUT_ 256

typedef unsigned long long u64;

// ---------- packed f32x2 FMA (full-rate fp32 on sm_103a; K packed into halves) ----------
__device__ __forceinline__ void f2fma(u64 &d, u64 a, u64 b) {
    asm("fma.rn.f32x2 %0, %1, %2, %0;" : "+l"(d) : "l"(a), "l"(b));
}
__device__ __forceinline__ float f2sum(u64 v) {
    unsigned lo, hi;
    asm("mov.b64 {%0, %1}, %2;" : "=r"(lo), "=r"(hi) : "l"(v));
    return __uint_as_float(lo) + __uint_as_float(hi);
}
__device__ __forceinline__ float sigmoidf_(float x) { return 1.0f / (1.0f + expf(-x)); }

// ---------- device scratch (no allocations allowed) ----------
__device__ float g_pre[(size_t)B_ * T_ * 3 * HID_];   // [m=b*T+t][z|r|h], bias folded
__device__ float g_h[2][B_ * HID_];                   // ping-pong hidden state
__device__ float g_z[B_ * HID_];                      // z gate, current step
__device__ float g_rh[B_ * HID_];                     // r*h, current step

// =====================================================================================
// Kernel 1: PRE = [x|c] @ [W_x;W_c](gate) + bias.  M=65536, N=1536, K=512.
// Tile 64x64, 256 threads, thread tile 4x4 (cols strided by 16). K-chunks of 32.
// =====================================================================================
__global__ __launch_bounds__(256) void pre_gemm_kernel(
    const float* __restrict__ x, const float* __restrict__ c,
    const float* __restrict__ wxz, const float* __restrict__ wcz, const float* __restrict__ bz,
    const float* __restrict__ wxr, const float* __restrict__ wcr, const float* __restrict__ br,
    const float* __restrict__ wxh, const float* __restrict__ wch, const float* __restrict__ bh)
{
    __shared__ __align__(16) float As[64][36];   // [row][k], 144B stride (16B aligned)
    __shared__ __align__(16) float Bs[64][36];   // [n_local][k]

    const int tid = threadIdx.x;
    const int m0 = blockIdx.y * 64;
    const int n0 = blockIdx.x * 64;
    const int gate = n0 >> 9;                    // 0:z 1:r 2:h
    const int nl0 = n0 & (HID_ - 1);

    const float* Wx   = (gate == 0) ? wxz : (gate == 1) ? wxr : wxh;
    const float* Wc   = (gate == 0) ? wcz : (gate == 1) ? wcr : wch;
    const float* bias = (gate == 0) ? bz  : (gate == 1) ? br  : bh;

    const int ttr = tid >> 4;        // 0..15 -> rows ttr*4..+3
    const int ttc = tid & 15;        // cols ttc + 16*p

    const int arow = tid >> 2;       // 0..63
    const int akq  = tid & 3;        // 2 float4 per thread (k offsets akq*4, 16+akq*4)
    const int bkr  = tid >> 3;       // 0..31  (k row)
    const int bnq  = tid & 7;        // 2 float4 -> 8 n columns

    u64 acc[4][4];
    #pragma unroll
    for (int i = 0; i < 4; i++)
        #pragma unroll
        for (int p = 0; p < 4; p++) acc[i][p] = 0ull;

    for (int k0 = 0; k0 < 512; k0 += 32) {
        const float* Asrc = (k0 < 256) ? x  : c;
        const float* Bsrc = (k0 < 256) ? Wx : Wc;
        const int kb = k0 & 255;

        float4 av0 = *(const float4*)&Asrc[(size_t)(m0 + arow) * IN_ + kb + akq * 4];
        float4 av1 = *(const float4*)&Asrc[(size_t)(m0 + arow) * IN_ + kb + 16 + akq * 4];
        float4 bv0 = *(const float4*)&Bsrc[(size_t)(kb + bkr) * HID_ + nl0 + bnq * 8];
        float4 bv1 = *(const float4*)&Bsrc[(size_t)(kb + bkr) * HID_ + nl0 + bnq * 8 + 4];

        __syncthreads();
        *(float4*)&As[arow][akq * 4]      = av0;
        *(float4*)&As[arow][16 + akq * 4] = av1;
        Bs[bnq * 8 + 0][bkr] = bv0.x; Bs[bnq * 8 + 1][bkr] = bv0.y;
        Bs[bnq * 8 + 2][bkr] = bv0.z; Bs[bnq * 8 + 3][bkr] = bv0.w;
        Bs[bnq * 8 + 4][bkr] = bv1.x; Bs[bnq * 8 + 5][bkr] = bv1.y;
        Bs[bnq * 8 + 6][bkr] = bv1.z; Bs[bnq * 8 + 7][bkr] = bv1.w;
        __syncthreads();

        #pragma unroll
        for (int q = 0; q < 8; q++) {
            ulonglong2 a[4], b[4];
            #pragma unroll
            for (int i = 0; i < 4; i++)
                a[i] = *(const ulonglong2*)&As[ttr * 4 + i][q * 4];
            #pragma unroll
            for (int p = 0; p < 4; p++)
                b[p] = *(const ulonglong2*)&Bs[ttc + 16 * p][q * 4];
            #pragma unroll
            for (int i = 0; i < 4; i++)
                #pragma unroll
                for (int p = 0; p < 4; p++) {
                    f2fma(acc[i][p], a[i].x, b[p].x);
                    f2fma(acc[i][p], a[i].y, b[p].y);
                }
        }
    }

    #pragma unroll
    for (int i = 0; i < 4; i++) {
        const int m = m0 + ttr * 4 + i;
        #pragma unroll
        for (int p = 0; p < 4; p++) {
            const int cl = ttc + 16 * p;
            const int j  = nl0 + cl;
            g_pre[(size_t)m * 1536 + n0 + cl] = f2sum(acc[i][p]) + bias[j];
        }
    }
}

// =====================================================================================
// Kernel 2 (per step): S = h_prev @ [w_hz | w_hr].  M=256(batch), N=1024, K=512.
// Tile 32x64, grid (16,8)=128 blocks. Epilogue: z=sigmoid(pre_z+S) ; rh=sigmoid(pre_r+S)*h.
// =====================================================================================
__global__ __launch_bounds__(256) void gate_kernel(
    const float* __restrict__ w_hz, const float* __restrict__ w_hr, int t)
{
    __shared__ __align__(16) float As[32][36];
    __shared__ __align__(16) float Bs[64][36];

    const float* __restrict__ hprev = g_h[t & 1];
    const int tid = threadIdx.x;
    const int m0 = blockIdx.y * 32;
    const int n0 = blockIdx.x * 64;
    const int isz = (n0 < HID_);
    const float* W = isz ? w_hz : w_hr;
    const int nl0 = n0 & (HID_ - 1);

    const int ttr = tid >> 4;      // rows ttr*2..+1
    const int ttc = tid & 15;      // cols ttc + 16*p

    const int arow = tid >> 3;     // 0..31
    const int akq  = tid & 7;      // k offset akq*4
    const int bkr  = tid >> 3;     // 0..31
    const int bnq  = tid & 7;      // 8 n columns

    u64 acc[2][4];
    #pragma unroll
    for (int i = 0; i < 2; i++)
        #pragma unroll
        for (int p = 0; p < 4; p++) acc[i][p] = 0ull;

    for (int k0 = 0; k0 < HID_; k0 += 32) {
        float4 av  = *(const float4*)&hprev[(size_t)(m0 + arow) * HID_ + k0 + akq * 4];
        float4 bv0 = *(const float4*)&W[(size_t)(k0 + bkr) * HID_ + nl0 + bnq * 8];
        float4 bv1 = *(const float4*)&W[(size_t)(k0 + bkr) * HID_ + nl0 + bnq * 8 + 4];

        __syncthreads();
        *(float4*)&As[arow][akq * 4] = av;
        Bs[bnq * 8 + 0][bkr] = bv0.x; Bs[bnq * 8 + 1][bkr] = bv0.y;
        Bs[bnq * 8 + 2][bkr] = bv0.z; Bs[bnq * 8 + 3][bkr] = bv0.w;
        Bs[bnq * 8 + 4][bkr] = bv1.x; Bs[bnq * 8 + 5][bkr] = bv1.y;
        Bs[bnq * 8 + 6][bkr] = bv1.z; Bs[bnq * 8 + 7][bkr] = bv1.w;
        __syncthreads();

        #pragma unroll
        for (int q = 0; q < 8; q++) {
            ulonglong2 a0 = *(const ulonglong2*)&As[ttr * 2 + 0][q * 4];
            ulonglong2 a1 = *(const ulonglong2*)&As[ttr * 2 + 1][q * 4];
            #pragma unroll
            for (int p = 0; p < 4; p++) {
                ulonglong2 bb = *(const ulonglong2*)&Bs[ttc + 16 * p][q * 4];
                f2fma(acc[0][p], a0.x, bb.x); f2fma(acc[0][p], a0.y, bb.y);
                f2fma(acc[1][p], a1.x, bb.x); f2fma(acc[1][p], a1.y, bb.y);
            }
        }
    }

    #pragma unroll
    for (int i = 0; i < 2; i++) {
        const int b = m0 + ttr * 2 + i;
        const size_t prow = ((size_t)b * T_ + t) * 1536;
        #pragma unroll
        for (int p = 0; p < 4; p++) {
            const int j = nl0 + ttc + 16 * p;
            const float s = f2sum(acc[i][p]);
            if (isz) {
                g_z[b * HID_ + j] = sigmoidf_(g_pre[prow + j] + s);
            } else {
                float r = sigmoidf_(g_pre[prow + HID_ + j] + s);
                g_rh[b * HID_ + j] = r * hprev[b * HID_ + j];
            }
        }
    }
}

// =====================================================================================
// Kernel 3 (per step): S = (r*h) @ w_hh.  M=256, N=512, K=512.
// Tile 32x32, grid (16,8)=128 blocks. Epilogue: h' = h + z*(tanh(pre_h+S) - h); write hs.
// =====================================================================================
__global__ __launch_bounds__(256) void cand_kernel(
    const float* __restrict__ w_hh, float* __restrict__ hs_out, int t)
{
    __shared__ __align__(16) float As[32][36];
    __shared__ __align__(16) float Bs[32][36];

    const float* __restrict__ hprev = g_h[t & 1];
    float* __restrict__ hnext = g_h[(t + 1) & 1];

    const int tid = threadIdx.x;
    const int m0 = blockIdx.y * 32;
    const int n0 = blockIdx.x * 32;

    const int ttr = tid >> 4;      // rows ttr*2..+1
    const int ttc = tid & 15;      // cols ttc + 16*p (p=0..1)

    const int arow = tid >> 3;     // 0..31
    const int akq  = tid & 7;
    const int bkr  = tid >> 3;     // 0..31
    const int bnq  = tid & 7;      // 1 float4 -> 4 n columns

    u64 acc[2][2];
    #pragma unroll
    for (int i = 0; i < 2; i++)
        #pragma unroll
        for (int p = 0; p < 2; p++) acc[i][p] = 0ull;

    for (int k0 = 0; k0 < HID_; k0 += 32) {
        float4 av = *(const float4*)&g_rh[(size_t)(m0 + arow) * HID_ + k0 + akq * 4];
        float4 bv = *(const float4*)&w_hh[(size_t)(k0 + bkr) * HID_ + n0 + bnq * 4];

        __syncthreads();
        *(float4*)&As[arow][akq * 4] = av;
        Bs[bnq * 4 + 0][bkr] = bv.x; Bs[bnq * 4 + 1][bkr] = bv.y;
        Bs[bnq * 4 + 2][bkr] = bv.z; Bs[bnq * 4 + 3][bkr] = bv.w;
        __syncthreads();

        #pragma unroll
        for (int q = 0; q < 8; q++) {
            ulonglong2 a0 = *(const ulonglong2*)&As[ttr * 2 + 0][q * 4];
            ulonglong2 a1 = *(const ulonglong2*)&As[ttr * 2 + 1][q * 4];
            #pragma unroll
            for (int p = 0; p < 2; p++) {
                ulonglong2 bb = *(const ulonglong2*)&Bs[ttc + 16 * p][q * 4];
                f2fma(acc[0][p], a0.x, bb.x); f2fma(acc[0][p], a0.y, bb.y);
                f2fma(acc[1][p], a1.x, bb.x); f2fma(acc[1][p], a1.y, bb.y);
            }
        }
    }

    #pragma unroll
    for (int i = 0; i < 2; i++) {
        const int b = m0 + ttr * 2 + i;
        const size_t prow = ((size_t)b * T_ + t) * 1536;
        #pragma unroll
        for (int p = 0; p < 2; p++) {
            const int j = n0 + ttc + 16 * p;
            const float s  = f2sum(acc[i][p]);
            const float ht = tanhf(g_pre[prow + 2 * HID_ + j] + s);
            const float ho = hprev[b * HID_ + j];
            const float z  = g_z[b * HID_ + j];
            const float hn = fmaf(z, ht - ho, ho);
            hnext[b * HID_ + j] = hn;
            hs_out[((size_t)b * T_ + t) * HID_ + j] = hn;
        }
    }
}

// =====================================================================================
// Kernel 4: out = relu(h_last @ w_out + b_out).  M=256, N=256, K=512. Tile 32x32.
// =====================================================================================
__global__ __launch_bounds__(256) void out_kernel(
    const float* __restrict__ w_out, const float* __restrict__ b_out,
    float* __restrict__ out)
{
    __shared__ __align__(16) float As[32][36];
    __shared__ __align__(16) float Bs[32][36];

    const float* __restrict__ hlast = g_h[0];   // T=256 even -> final state in buffer 0

    const int tid = threadIdx.x;
    const int m0 = blockIdx.y * 32;
    const int n0 = blockIdx.x * 32;

    const int ttr = tid >> 4;
    const int ttc = tid & 15;
    const int arow = tid >> 3;
    const int akq  = tid & 7;
    const int bkr  = tid >> 3;
    const int bnq  = tid & 7;

    u64 acc[2][2];
    #pragma unroll
    for (int i = 0; i < 2; i++)
        #pragma unroll
        for (int p = 0; p < 2; p++) acc[i][p] = 0ull;

    for (int k0 = 0; k0 < HID_; k0 += 32) {
        float4 av = *(const float4*)&hlast[(size_t)(m0 + arow) * HID_ + k0 + akq * 4];
        float4 bv = *(const float4*)&w_out[(size_t)(k0 + bkr) * OUT_ + n0 + bnq * 4];

        __syncthreads();
        *(float4*)&As[arow][akq * 4] = av;
        Bs[bnq * 4 + 0][bkr] = bv.x; Bs[bnq * 4 + 1][bkr] = bv.y;
        Bs[bnq * 4 + 2][bkr] = bv.z; Bs[bnq * 4 + 3][bkr] = bv.w;
        __syncthreads();

        #pragma unroll
        for (int q = 0; q < 8; q++) {
            ulonglong2 a0 = *(const ulonglong2*)&As[ttr * 2 + 0][q * 4];
            ulonglong2 a1 = *(const ulonglong2*)&As[ttr * 2 + 1][q * 4];
            #pragma unroll
            for (int p = 0; p < 2; p++) {
                ulonglong2 bb = *(const ulonglong2*)&Bs[ttc + 16 * p][q * 4];
                f2fma(acc[0][p], a0.x, bb.x); f2fma(acc[0][p], a0.y, bb.y);
                f2fma(acc[1][p], a1.x, bb.x); f2fma(acc[1][p], a1.y, bb.y);
            }
        }
    }

    #pragma unroll
    for (int i = 0; i < 2; i++) {
        const int b = m0 + ttr * 2 + i;
        #pragma unroll
        for (int p = 0; p < 2; p++) {
            const int j = n0 + ttc + 16 * p;
            const float s = f2sum(acc[i][p]) + b_out[j];
            out[(size_t)b * OUT_ + j] = fmaxf(s, 0.0f);
        }
    }
}

// =====================================================================================
extern "C" void kernel_launch(void* const* d_in, const int* in_sizes, int n_in,
                              void* d_out, int out_size)
{
    const float* x     = (const float*)d_in[0];
    const float* c     = (const float*)d_in[1];
    const float* h0    = (const float*)d_in[2];
    const float* w_xr  = (const float*)d_in[3];
    const float* w_hr  = (const float*)d_in[4];
    const float* w_cr  = (const float*)d_in[5];
    const float* w_xz  = (const float*)d_in[6];
    const float* w_hz  = (const float*)d_in[7];
    const float* w_cz  = (const float*)d_in[8];
    const float* w_xh  = (const float*)d_in[9];
    const float* w_hh  = (const float*)d_in[10];
    const float* w_ch  = (const float*)d_in[11];
    const float* b_r   = (const float*)d_in[12];
    const float* b_z   = (const float*)d_in[13];
    const float* b_h   = (const float*)d_in[14];
    const float* w_out = (const float*)d_in[15];
    const float* b_out = (const float*)d_in[16];

    float* out = (float*)d_out;                 // [B, OUT] first
    float* hs  = out + (size_t)B_ * OUT_;       // then [B, T, HID]

    // h0 -> g_h[0]
    cudaMemcpyToSymbolAsync(g_h, h0, (size_t)B_ * HID_ * sizeof(float), 0,
                            cudaMemcpyDeviceToDevice, 0);

    pre_gemm_kernel<<<dim3(24, 1024), 256>>>(x, c,
                                             w_xz, w_cz, b_z,
                                             w_xr, w_cr, b_r,
                                             w_xh, w_ch, b_h);

    for (int t = 0; t < T_; t++) {
        gate_kernel<<<dim3(16, 8), 256>>>(w_hz, w_hr, t);
        cand_kernel<<<dim3(16, 8), 256>>>(w_hh, hs, t);
    }

    out_kernel<<<dim3(8, 8), 256>>>(w_out, b_out, out);
}

// round 3
// speedup vs baseline: 1.1320x; 1.1320x over previous
#include <cuda_runtime.h>
#include <math.h>

#define B_   256
#define T_   256
#define IN_  256
#define HID_ 512
#define OUT_ 256
#define NBLK 128

typedef unsigned long long u64;

// ---------- packed f32x2 FMA (K packed into the two halves) ----------
__device__ __forceinline__ void f2fma(u64 &d, u64 a, u64 b) {
    asm("fma.rn.f32x2 %0, %1, %2, %0;" : "+l"(d) : "l"(a), "l"(b));
}
__device__ __forceinline__ float f2sum(u64 v) {
    unsigned lo, hi;
    asm("mov.b64 {%0, %1}, %2;" : "=r"(lo), "=r"(hi) : "l"(v));
    return __uint_as_float(lo) + __uint_as_float(hi);
}
__device__ __forceinline__ float sigmoidf_(float x) { return 1.0f / (1.0f + expf(-x)); }

// ---------- device scratch ----------
__device__ float g_pre[(size_t)B_ * T_ * 3 * HID_];   // [m][z|r|h], bias folded
__device__ float g_h[2][B_ * HID_];
__device__ float g_z[B_ * HID_];
__device__ float g_rh[B_ * HID_];
__device__ unsigned g_cnt;     // zero-init
__device__ unsigned g_epoch;   // monotonic across replays

// =====================================================================================
// Kernel 1: PRE = [x|c] @ [W_x;W_c](gate) + bias.  (unchanged from R1 — passed)
// =====================================================================================
__global__ __launch_bounds__(256) void pre_gemm_kernel(
    const float* __restrict__ x, const float* __restrict__ c,
    const float* __restrict__ wxz, const float* __restrict__ wcz, const float* __restrict__ bz,
    const float* __restrict__ wxr, const float* __restrict__ wcr, const float* __restrict__ br,
    const float* __restrict__ wxh, const float* __restrict__ wch, const float* __restrict__ bh)
{
    __shared__ __align__(16) float As[64][36];
    __shared__ __align__(16) float Bs[64][36];

    const int tid = threadIdx.x;
    const int m0 = blockIdx.y * 64;
    const int n0 = blockIdx.x * 64;
    const int gate = n0 >> 9;
    const int nl0 = n0 & (HID_ - 1);

    const float* Wx   = (gate == 0) ? wxz : (gate == 1) ? wxr : wxh;
    const float* Wc   = (gate == 0) ? wcz : (gate == 1) ? wcr : wch;
    const float* bias = (gate == 0) ? bz  : (gate == 1) ? br  : bh;

    const int ttr = tid >> 4;
    const int ttc = tid & 15;
    const int arow = tid >> 2;
    const int akq  = tid & 3;
    const int bkr  = tid >> 3;
    const int bnq  = tid & 7;

    u64 acc[4][4];
    #pragma unroll
    for (int i = 0; i < 4; i++)
        #pragma unroll
        for (int p = 0; p < 4; p++) acc[i][p] = 0ull;

    for (int k0 = 0; k0 < 512; k0 += 32) {
        const float* Asrc = (k0 < 256) ? x  : c;
        const float* Bsrc = (k0 < 256) ? Wx : Wc;
        const int kb = k0 & 255;

        float4 av0 = *(const float4*)&Asrc[(size_t)(m0 + arow) * IN_ + kb + akq * 4];
        float4 av1 = *(const float4*)&Asrc[(size_t)(m0 + arow) * IN_ + kb + 16 + akq * 4];
        float4 bv0 = *(const float4*)&Bsrc[(size_t)(kb + bkr) * HID_ + nl0 + bnq * 8];
        float4 bv1 = *(const float4*)&Bsrc[(size_t)(kb + bkr) * HID_ + nl0 + bnq * 8 + 4];

        __syncthreads();
        *(float4*)&As[arow][akq * 4]      = av0;
        *(float4*)&As[arow][16 + akq * 4] = av1;
        Bs[bnq * 8 + 0][bkr] = bv0.x; Bs[bnq * 8 + 1][bkr] = bv0.y;
        Bs[bnq * 8 + 2][bkr] = bv0.z; Bs[bnq * 8 + 3][bkr] = bv0.w;
        Bs[bnq * 8 + 4][bkr] = bv1.x; Bs[bnq * 8 + 5][bkr] = bv1.y;
        Bs[bnq * 8 + 6][bkr] = bv1.z; Bs[bnq * 8 + 7][bkr] = bv1.w;
        __syncthreads();

        #pragma unroll
        for (int q = 0; q < 8; q++) {
            ulonglong2 a[4], b[4];
            #pragma unroll
            for (int i = 0; i < 4; i++)
                a[i] = *(const ulonglong2*)&As[ttr * 4 + i][q * 4];
            #pragma unroll
            for (int p = 0; p < 4; p++)
                b[p] = *(const ulonglong2*)&Bs[ttc + 16 * p][q * 4];
            #pragma unroll
            for (int i = 0; i < 4; i++)
                #pragma unroll
                for (int p = 0; p < 4; p++) {
                    f2fma(acc[i][p], a[i].x, b[p].x);
                    f2fma(acc[i][p], a[i].y, b[p].y);
                }
        }
    }

    #pragma unroll
    for (int i = 0; i < 4; i++) {
        const int m = m0 + ttr * 4 + i;
        #pragma unroll
        for (int p = 0; p < 4; p++) {
            const int cl = ttc + 16 * p;
            const int j  = nl0 + cl;
            g_pre[(size_t)m * 1536 + n0 + cl] = f2sum(acc[i][p]) + bias[j];
        }
    }
}

// =====================================================================================
// Persistent scan kernel: 128 blocks (8 m-tiles x 16 n-tiles), 256 threads, 1 CTA/SM.
// Weights live in smem for all 256 steps. Two grid barriers per step.
// =====================================================================================
__device__ __forceinline__ void gbar(unsigned want)
{
    __threadfence();
    __syncthreads();
    if (threadIdx.x == 0) {
        unsigned old = atomicAdd(&g_cnt, 1u);
        if (old == NBLK - 1) {
            g_cnt = 0;
            __threadfence();
            atomicAdd(&g_epoch, 1u);
        } else {
            unsigned v;
            do { v = *(volatile unsigned*)&g_epoch; } while ((int)(v - want) < 0);
        }
    }
    __syncthreads();
}

#define WA_F (64 * 516)
#define WB_F (32 * 516)
#define AS_F (32 * 132)
#define SCAN_SMEM ((WA_F + WB_F + AS_F) * sizeof(float))

__global__ __launch_bounds__(256, 1) void scan_kernel(
    const float* __restrict__ w_hz, const float* __restrict__ w_hr,
    const float* __restrict__ w_hh, float* __restrict__ hs_out)
{
    extern __shared__ float smem[];
    float* wA = smem;                 // [64][516]  cols of [Whz|Whr], k-contig
    float* wB = smem + WA_F;          // [32][516]  cols of Whh
    float* As = smem + WA_F + WB_F;   // [32][132]  A k-chunk staging

    const int tid = threadIdx.x;
    const int bm = blockIdx.x >> 4;        // 0..7
    const int bn = blockIdx.x & 15;        // 0..15
    const int m0 = bm * 32;

    const int ttr = tid & 15;              // row pair (ttr, ttr+16)
    const int ttc = tid >> 4;              // col group

    // ---- one-time weight load into smem (transposed: [n_local][k]) ----
    {
        const float* WsrcA = (bn < 8) ? w_hz : w_hr;
        const int colA0 = (bn & 7) * 64;
        const int col = tid & 63, kst = tid >> 6;
        for (int k = kst; k < HID_; k += 4)
            wA[col * 516 + k] = WsrcA[(size_t)k * HID_ + colA0 + col];

        const int colB0 = bn * 32;
        const int colb = tid & 31, kst2 = tid >> 5;
        for (int k = kst2; k < HID_; k += 8)
            wB[colb * 516 + k] = w_hh[(size_t)k * HID_ + colB0 + colb];
    }

    unsigned ep_base = 0;
    if (tid == 0) ep_base = *(volatile unsigned*)&g_epoch;
    unsigned bar_i = 0;

    const bool is_z = (bn < 8);
    const int jbaseA = (bn & 7) * 64;
    const int jbaseB = bn * 32;
    const int srow = tid >> 3;             // staging row 0..31
    const int sk   = (tid & 7) * 4;        // staging k offset

    for (int t = 0; t < T_; t++) {
        const float* __restrict__ hprev = g_h[t & 1];
        float* __restrict__ hnext = g_h[(t + 1) & 1];

        // ================= phase A: S = h @ Wslice (64 cols) =================
        u64 acc[2][4];
        #pragma unroll
        for (int i = 0; i < 2; i++)
            #pragma unroll
            for (int p = 0; p < 4; p++) acc[i][p] = 0ull;

        for (int ch = 0; ch < 4; ch++) {
            const int k0 = ch * 128;
            __syncthreads();
            #pragma unroll
            for (int ps = 0; ps < 4; ps++) {
                float4 v = __ldcg((const float4*)&hprev[(size_t)(m0 + srow) * HID_ + k0 + ps * 32 + sk]);
                *(float4*)&As[srow * 132 + ps * 32 + sk] = v;
            }
            __syncthreads();
            #pragma unroll 8
            for (int kg = 0; kg < 32; kg++) {
                ulonglong2 a0 = *(const ulonglong2*)&As[ttr * 132 + kg * 4];
                ulonglong2 a1 = *(const ulonglong2*)&As[(ttr + 16) * 132 + kg * 4];
                #pragma unroll
                for (int p = 0; p < 4; p++) {
                    ulonglong2 b = *(const ulonglong2*)&wA[(ttc + 16 * p) * 516 + k0 + kg * 4];
                    f2fma(acc[0][p], a0.x, b.x); f2fma(acc[0][p], a0.y, b.y);
                    f2fma(acc[1][p], a1.x, b.x); f2fma(acc[1][p], a1.y, b.y);
                }
            }
        }

        #pragma unroll
        for (int i = 0; i < 2; i++) {
            const int m = m0 + ttr + 16 * i;
            const size_t prow = ((size_t)m * T_ + t) * 1536;
            #pragma unroll
            for (int p = 0; p < 4; p++) {
                const int j = jbaseA + ttc + 16 * p;
                const float s = f2sum(acc[i][p]);
                if (is_z) {
                    g_z[m * HID_ + j] = sigmoidf_(__ldg(&g_pre[prow + j]) + s);
                } else {
                    float r = sigmoidf_(__ldg(&g_pre[prow + HID_ + j]) + s);
                    g_rh[m * HID_ + j] = r * __ldcg(&hprev[m * HID_ + j]);
                }
            }
        }
        gbar(ep_base + (++bar_i));

        // ================= phase B: S = rh @ Whh-slice (32 cols) =================
        u64 accB[2][2];
        #pragma unroll
        for (int i = 0; i < 2; i++)
            #pragma unroll
            for (int p = 0; p < 2; p++) accB[i][p] = 0ull;

        for (int ch = 0; ch < 4; ch++) {
            const int k0 = ch * 128;
            __syncthreads();
            #pragma unroll
            for (int ps = 0; ps < 4; ps++) {
                float4 v = __ldcg((const float4*)&g_rh[(size_t)(m0 + srow) * HID_ + k0 + ps * 32 + sk]);
                *(float4*)&As[srow * 132 + ps * 32 + sk] = v;
            }
            __syncthreads();
            #pragma unroll 8
            for (int kg = 0; kg < 32; kg++) {
                ulonglong2 a0 = *(const ulonglong2*)&As[ttr * 132 + kg * 4];
                ulonglong2 a1 = *(const ulonglong2*)&As[(ttr + 16) * 132 + kg * 4];
                #pragma unroll
                for (int p = 0; p < 2; p++) {
                    ulonglong2 b = *(const ulonglong2*)&wB[(ttc + 16 * p) * 516 + k0 + kg * 4];
                    f2fma(accB[0][p], a0.x, b.x); f2fma(accB[0][p], a0.y, b.y);
                    f2fma(accB[1][p], a1.x, b.x); f2fma(accB[1][p], a1.y, b.y);
                }
            }
        }

        #pragma unroll
        for (int i = 0; i < 2; i++) {
            const int m = m0 + ttr + 16 * i;
            const size_t prow = ((size_t)m * T_ + t) * 1536;
            #pragma unroll
            for (int p = 0; p < 2; p++) {
                const int j = jbaseB + ttc + 16 * p;
                const float s  = f2sum(accB[i][p]);
                const float ht = tanhf(__ldg(&g_pre[prow + 2 * HID_ + j]) + s);
                const float ho = __ldcg(&hprev[m * HID_ + j]);
                const float z  = __ldcg(&g_z[m * HID_ + j]);
                const float hn = fmaf(z, ht - ho, ho);
                hnext[m * HID_ + j] = hn;
                hs_out[((size_t)m * T_ + t) * HID_ + j] = hn;
            }
        }
        if (t < T_ - 1) gbar(ep_base + (++bar_i));
    }
}

// =====================================================================================
// Kernel 4: out = relu(h_last @ w_out + b_out).  (unchanged from R1)
// =====================================================================================
__global__ __launch_bounds__(256) void out_kernel(
    const float* __restrict__ w_out, const float* __restrict__ b_out,
    float* __restrict__ out)
{
    __shared__ __align__(16) float As[32][36];
    __shared__ __align__(16) float Bs[32][36];

    const float* __restrict__ hlast = g_h[0];

    const int tid = threadIdx.x;
    const int m0 = blockIdx.y * 32;
    const int n0 = blockIdx.x * 32;

    const int ttr = tid >> 4;
    const int ttc = tid & 15;
    const int arow = tid >> 3;
    const int akq  = tid & 7;
    const int bkr  = tid >> 3;
    const int bnq  = tid & 7;

    u64 acc[2][2];
    #pragma unroll
    for (int i = 0; i < 2; i++)
        #pragma unroll
        for (int p = 0; p < 2; p++) acc[i][p] = 0ull;

    for (int k0 = 0; k0 < HID_; k0 += 32) {
        float4 av = *(const float4*)&hlast[(size_t)(m0 + arow) * HID_ + k0 + akq * 4];
        float4 bv = *(const float4*)&w_out[(size_t)(k0 + bkr) * OUT_ + n0 + bnq * 4];

        __syncthreads();
        *(float4*)&As[arow][akq * 4] = av;
        Bs[bnq * 4 + 0][bkr] = bv.x; Bs[bnq * 4 + 1][bkr] = bv.y;
        Bs[bnq * 4 + 2][bkr] = bv.z; Bs[bnq * 4 + 3][bkr] = bv.w;
        __syncthreads();

        #pragma unroll
        for (int q = 0; q < 8; q++) {
            ulonglong2 a0 = *(const ulonglong2*)&As[ttr * 2 + 0][q * 4];
            ulonglong2 a1 = *(const ulonglong2*)&As[ttr * 2 + 1][q * 4];
            #pragma unroll
            for (int p = 0; p < 2; p++) {
                ulonglong2 bb = *(const ulonglong2*)&Bs[ttc + 16 * p][q * 4];
                f2fma(acc[0][p], a0.x, bb.x); f2fma(acc[0][p], a0.y, bb.y);
                f2fma(acc[1][p], a1.x, bb.x); f2fma(acc[1][p], a1.y, bb.y);
            }
        }
    }

    #pragma unroll
    for (int i = 0; i < 2; i++) {
        const int b = m0 + ttr * 2 + i;
        #pragma unroll
        for (int p = 0; p < 2; p++) {
            const int j = n0 + ttc + 16 * p;
            const float s = f2sum(acc[i][p]) + b_out[j];
            out[(size_t)b * OUT_ + j] = fmaxf(s, 0.0f);
        }
    }
}

// =====================================================================================
extern "C" void kernel_launch(void* const* d_in, const int* in_sizes, int n_in,
                              void* d_out, int out_size)
{
    const float* x     = (const float*)d_in[0];
    const float* c     = (const float*)d_in[1];
    const float* h0    = (const float*)d_in[2];
    const float* w_xr  = (const float*)d_in[3];
    const float* w_hr  = (const float*)d_in[4];
    const float* w_cr  = (const float*)d_in[5];
    const float* w_xz  = (const float*)d_in[6];
    const float* w_hz  = (const float*)d_in[7];
    const float* w_cz  = (const float*)d_in[8];
    const float* w_xh  = (const float*)d_in[9];
    const float* w_hh  = (const float*)d_in[10];
    const float* w_ch  = (const float*)d_in[11];
    const float* b_r   = (const float*)d_in[12];
    const float* b_z   = (const float*)d_in[13];
    const float* b_h   = (const float*)d_in[14];
    const float* w_out = (const float*)d_in[15];
    const float* b_out = (const float*)d_in[16];

    float* out = (float*)d_out;                 // [B, OUT] first
    float* hs  = out + (size_t)B_ * OUT_;       // then [B, T, HID]

    static int smem_set = 0;
    if (!smem_set) {
        cudaFuncSetAttribute(scan_kernel, cudaFuncAttributeMaxDynamicSharedMemorySize,
                             (int)SCAN_SMEM);
        smem_set = 1;
    }

    cudaMemcpyToSymbolAsync(g_h, h0, (size_t)B_ * HID_ * sizeof(float), 0,
                            cudaMemcpyDeviceToDevice, 0);

    pre_gemm_kernel<<<dim3(24, 1024), 256>>>(x, c,
                                             w_xz, w_cz, b_z,
                                             w_xr, w_cr, b_r,
                                             w_xh, w_ch, b_h);

    scan_kernel<<<NBLK, 256, SCAN_SMEM>>>(w_hz, w_hr, w_hh, hs);

    out_kernel<<<dim3(8, 8), 256>>>(w_out, b_out, out);
}

// round 4
// speedup vs baseline: 1.6133x; 1.4252x over previous
#include <cuda_runtime.h>
#include <math.h>

#define B_   256
#define T_   256
#define IN_  256
#define HID_ 512
#define OUT_ 256
#define NBLK 128

typedef unsigned long long u64;

// ---------- packed f32x2 FMA (K packed into the two halves) ----------
__device__ __forceinline__ void f2fma(u64 &d, u64 a, u64 b) {
    asm("fma.rn.f32x2 %0, %1, %2, %0;" : "+l"(d) : "l"(a), "l"(b));
}
__device__ __forceinline__ float f2sum(u64 v) {
    unsigned lo, hi;
    asm("mov.b64 {%0, %1}, %2;" : "=r"(lo), "=r"(hi) : "l"(v));
    return __uint_as_float(lo) + __uint_as_float(hi);
}
__device__ __forceinline__ float sigmoidf_(float x) { return 1.0f / (1.0f + expf(-x)); }

// ---------- device scratch ----------
__device__ float g_pre[(size_t)B_ * T_ * 3 * HID_];   // [m][z|r|h], bias folded
__device__ float g_h[2][B_ * HID_];
__device__ float g_rh[B_ * HID_];
__device__ unsigned g_flags[NBLK * 32];               // 128B-spaced flags, zero-init, monotonic

// =====================================================================================
// Kernel 1: PRE = [x|c] @ [W_x;W_c](gate) + bias.  M=65536, N=1536, K=512.
// Tile 64x64, 256 threads, 4x4 f32x2 thread tile. Register-prefetched chunks,
// XOR-swizzled B smem store (conflict-free).
// =====================================================================================
__global__ __launch_bounds__(256) void pre_gemm_kernel(
    const float* __restrict__ x, const float* __restrict__ c,
    const float* __restrict__ wxz, const float* __restrict__ wcz, const float* __restrict__ bz,
    const float* __restrict__ wxr, const float* __restrict__ wcr, const float* __restrict__ br,
    const float* __restrict__ wxh, const float* __restrict__ wch, const float* __restrict__ bh)
{
    __shared__ __align__(16) float As[64][36];
    __shared__ __align__(16) float Bs[64 * 36];      // [col][k], k-groups XOR-swizzled by col>>3

    const int tid = threadIdx.x;
    const int m0 = blockIdx.y * 64;
    const int n0 = blockIdx.x * 64;
    const int gate = n0 >> 9;
    const int nl0 = n0 & (HID_ - 1);

    const float* Wx   = (gate == 0) ? wxz : (gate == 1) ? wxr : wxh;
    const float* Wc   = (gate == 0) ? wcz : (gate == 1) ? wcr : wch;
    const float* bias = (gate == 0) ? bz  : (gate == 1) ? br  : bh;

    const int ttr = tid >> 4;        // 0..15
    const int ttc = tid & 15;        // 0..15
    const int arow = tid >> 2;       // 0..63
    const int akq  = tid & 3;        // 0..3
    const int bkr  = tid >> 3;       // 0..31 (k row within chunk)
    const int bnq  = tid & 7;        // 0..7  (8-col group)

    u64 acc[4][4];
    #pragma unroll
    for (int i = 0; i < 4; i++)
        #pragma unroll
        for (int p = 0; p < 4; p++) acc[i][p] = 0ull;

    // prologue: chunk 0 into registers
    float4 av0 = *(const float4*)&x[(size_t)(m0 + arow) * IN_ + akq * 4];
    float4 av1 = *(const float4*)&x[(size_t)(m0 + arow) * IN_ + 16 + akq * 4];
    float4 bv0 = *(const float4*)&Wx[(size_t)bkr * HID_ + nl0 + bnq * 8];
    float4 bv1 = *(const float4*)&Wx[(size_t)bkr * HID_ + nl0 + bnq * 8 + 4];

    const int bg = bkr >> 2;         // k-group 0..7
    const int bw = bkr & 3;          // k within group
    const int bsw = ((bg ^ bnq) << 2) + bw;   // swizzled offset within row

    for (int k0 = 0; k0 < 512; k0 += 32) {
        __syncthreads();
        *(float4*)&As[arow][akq * 4]      = av0;
        *(float4*)&As[arow][16 + akq * 4] = av1;
        {
            float tmp[8] = {bv0.x, bv0.y, bv0.z, bv0.w, bv1.x, bv1.y, bv1.z, bv1.w};
            #pragma unroll
            for (int c2 = 0; c2 < 8; c2++)
                Bs[(bnq * 8 + c2) * 36 + bsw] = tmp[c2];
        }
        __syncthreads();

        if (k0 + 32 < 512) {
            const int kn = k0 + 32;
            const float* Asrc = (kn < 256) ? x  : c;
            const float* Bsrc = (kn < 256) ? Wx : Wc;
            const int kb = kn & 255;
            av0 = *(const float4*)&Asrc[(size_t)(m0 + arow) * IN_ + kb + akq * 4];
            av1 = *(const float4*)&Asrc[(size_t)(m0 + arow) * IN_ + kb + 16 + akq * 4];
            bv0 = *(const float4*)&Bsrc[(size_t)(kb + bkr) * HID_ + nl0 + bnq * 8];
            bv1 = *(const float4*)&Bsrc[(size_t)(kb + bkr) * HID_ + nl0 + bnq * 8 + 4];
        }

        #pragma unroll
        for (int q = 0; q < 8; q++) {
            ulonglong2 a[4];
            #pragma unroll
            for (int i = 0; i < 4; i++)
                a[i] = *(const ulonglong2*)&As[ttr * 4 + i][q * 4];
            #pragma unroll
            for (int p = 0; p < 4; p++) {
                const int colp = ttc + 16 * p;
                ulonglong2 b = *(const ulonglong2*)&Bs[colp * 36 + ((q ^ (colp >> 3)) << 2)];
                #pragma unroll
                for (int i = 0; i < 4; i++) {
                    f2fma(acc[i][p], a[i].x, b.x);
                    f2fma(acc[i][p], a[i].y, b.y);
                }
            }
        }
    }

    #pragma unroll
    for (int i = 0; i < 4; i++) {
        const int m = m0 + ttr * 4 + i;
        #pragma unroll
        for (int p = 0; p < 4; p++) {
            const int cl = ttc + 16 * p;
            const int j  = nl0 + cl;
            g_pre[(size_t)m * 1536 + n0 + cl] = f2sum(acc[i][p]) + bias[j];
        }
    }
}

// =====================================================================================
// Flag-based grid barrier: one 128B-spaced flag per block, release/acquire, no atomics.
// =====================================================================================
__device__ __forceinline__ void gbar(unsigned want)
{
    __syncthreads();
    if (threadIdx.x == 0) {
        asm volatile("st.release.gpu.global.u32 [%0], %1;"
                     :: "l"(&g_flags[blockIdx.x * 32]), "r"(want) : "memory");
    }
    if (threadIdx.x < NBLK) {
        unsigned v;
        do {
            asm volatile("ld.acquire.gpu.global.u32 %0, [%1];"
                         : "=r"(v) : "l"(&g_flags[threadIdx.x * 32]) : "memory");
        } while ((int)(v - want) < 0);
    }
    __syncthreads();
}

// =====================================================================================
// Persistent scan kernel: 128 blocks = 8 m-tiles (32 rows) x 16 col-tiles (32 cols).
// Block computes BOTH z and r for its 32 cols (z kept in regs), then h-candidate.
// Weights in smem for all 256 steps; staged h/rh chunks software-pipelined.
// =====================================================================================
#define SC_WZR_F (64 * 516)
#define SC_WH_F  (32 * 516)
#define SC_AS_F  (32 * 132)
#define SCAN_SMEM ((SC_WZR_F + SC_WH_F + SC_AS_F) * sizeof(float))

__global__ __launch_bounds__(256, 1) void scan_kernel(
    const float* __restrict__ w_hz, const float* __restrict__ w_hr,
    const float* __restrict__ w_hh, float* __restrict__ hs_out)
{
    extern __shared__ float sm[];
    float* wZR = sm;                         // [64][516]: cols 0-31 = Whz slice, 32-63 = Whr slice
    float* wH  = sm + SC_WZR_F;              // [32][516]: Whh slice
    float* As  = sm + SC_WZR_F + SC_WH_F;    // [32][132] staging

    const int tid = threadIdx.x;
    const int bid = blockIdx.x;
    const int bm = bid >> 4;                 // 0..7
    const int bn = bid & 15;                 // 0..15
    const int m0 = bm * 32;
    const int j0 = bn * 32;

    // ---- one-time weight load (transposed to [col][k]) ----
    for (int idx = tid; idx < 512 * 8; idx += 256) {
        const int k  = idx >> 3;
        const int c4 = (idx & 7) * 4;
        float4 vz = *(const float4*)&w_hz[(size_t)k * HID_ + j0 + c4];
        float4 vr = *(const float4*)&w_hr[(size_t)k * HID_ + j0 + c4];
        float4 vh = *(const float4*)&w_hh[(size_t)k * HID_ + j0 + c4];
        wZR[(c4 + 0) * 516 + k] = vz.x; wZR[(c4 + 1) * 516 + k] = vz.y;
        wZR[(c4 + 2) * 516 + k] = vz.z; wZR[(c4 + 3) * 516 + k] = vz.w;
        wZR[(32 + c4 + 0) * 516 + k] = vr.x; wZR[(32 + c4 + 1) * 516 + k] = vr.y;
        wZR[(32 + c4 + 2) * 516 + k] = vr.z; wZR[(32 + c4 + 3) * 516 + k] = vr.w;
        wH[(c4 + 0) * 516 + k] = vh.x; wH[(c4 + 1) * 516 + k] = vh.y;
        wH[(c4 + 2) * 516 + k] = vh.z; wH[(c4 + 3) * 516 + k] = vh.w;
    }

    __shared__ unsigned s_base;
    if (tid == 0) s_base = *(volatile unsigned*)&g_flags[bid * 32];
    __syncthreads();
    const unsigned base = s_base;
    unsigned nbar = 0;

    // compute mapping: warp = 4 rows x 8 cols; block rows = ttr + 8u (u=0..3)
    const int wid  = tid >> 5, lane = tid & 31;
    const int ttr  = (wid >> 2) * 4 + (lane >> 3);   // 0..7
    const int col  = (wid & 3) * 8 + (lane & 7);     // 0..31
    const int j    = j0 + col;

    // staging mapping: 32 rows x 32 floats per chunk-quarter; XOR lane->granule for
    // conflict-free STS (slot = srow + g16 distinct within each srow group)
    const int srow = tid >> 3;
    const int sk   = (((tid & 7) ^ (srow & 7)) * 4);

    for (int t = 0; t < T_; t++) {
        const float* __restrict__ hprev = g_h[t & 1];
        float* __restrict__ hnext = g_h[(t + 1) & 1];

        // ---- epilogue prefetch (pre is static; hprev valid after prior barrier) ----
        float pz[4], pr[4], ph[4], hv[4];
        #pragma unroll
        for (int u = 0; u < 4; u++) {
            const int m = m0 + ttr + 8 * u;
            const size_t prow = ((size_t)m * T_ + t) * 1536;
            pz[u] = __ldg(&g_pre[prow + j]);
            pr[u] = __ldg(&g_pre[prow + 512 + j]);
            ph[u] = __ldg(&g_pre[prow + 1024 + j]);
            hv[u] = __ldcg(&hprev[m * HID_ + j]);
        }

        // ================= phase A: Sz,Sr = h @ [Whz|Whr] slice =================
        u64 az[4], ar[4];
        #pragma unroll
        for (int u = 0; u < 4; u++) { az[u] = 0ull; ar[u] = 0ull; }

        float4 r4[4];
        #pragma unroll
        for (int ps = 0; ps < 4; ps++)
            r4[ps] = __ldcg((const float4*)&hprev[(size_t)(m0 + srow) * HID_ + ps * 32 + sk]);

        for (int ch = 0; ch < 4; ch++) {
            const int k0 = ch * 128;
            __syncthreads();
            #pragma unroll
            for (int ps = 0; ps < 4; ps++)
                *(float4*)&As[srow * 132 + ps * 32 + sk] = r4[ps];
            __syncthreads();
            if (ch < 3) {
                #pragma unroll
                for (int ps = 0; ps < 4; ps++)
                    r4[ps] = __ldcg((const float4*)&hprev[(size_t)(m0 + srow) * HID_ + k0 + 128 + ps * 32 + sk]);
            }
            #pragma unroll 8
            for (int kg = 0; kg < 32; kg++) {
                ulonglong2 bz = *(const ulonglong2*)&wZR[col * 516 + k0 + kg * 4];
                ulonglong2 br2 = *(const ulonglong2*)&wZR[(col + 32) * 516 + k0 + kg * 4];
                #pragma unroll
                for (int u = 0; u < 4; u++) {
                    ulonglong2 a = *(const ulonglong2*)&As[(ttr + 8 * u) * 132 + kg * 4];
                    f2fma(az[u], a.x, bz.x); f2fma(az[u], a.y, bz.y);
                    f2fma(ar[u], a.x, br2.x); f2fma(ar[u], a.y, br2.y);
                }
            }
        }

        float zloc[4];
        #pragma unroll
        for (int u = 0; u < 4; u++) {
            const int m = m0 + ttr + 8 * u;
            zloc[u] = sigmoidf_(pz[u] + f2sum(az[u]));
            const float r = sigmoidf_(pr[u] + f2sum(ar[u]));
            g_rh[m * HID_ + j] = r * hv[u];
        }
        gbar(base + (++nbar));

        // ================= phase B: Sh = rh @ Whh slice =================
        u64 ah[4];
        #pragma unroll
        for (int u = 0; u < 4; u++) ah[u] = 0ull;

        #pragma unroll
        for (int ps = 0; ps < 4; ps++)
            r4[ps] = __ldcg((const float4*)&g_rh[(size_t)(m0 + srow) * HID_ + ps * 32 + sk]);

        for (int ch = 0; ch < 4; ch++) {
            const int k0 = ch * 128;
            __syncthreads();
            #pragma unroll
            for (int ps = 0; ps < 4; ps++)
                *(float4*)&As[srow * 132 + ps * 32 + sk] = r4[ps];
            __syncthreads();
            if (ch < 3) {
                #pragma unroll
                for (int ps = 0; ps < 4; ps++)
                    r4[ps] = __ldcg((const float4*)&g_rh[(size_t)(m0 + srow) * HID_ + k0 + 128 + ps * 32 + sk]);
            }
            #pragma unroll 8
            for (int kg = 0; kg < 32; kg++) {
                ulonglong2 bh2 = *(const ulonglong2*)&wH[col * 516 + k0 + kg * 4];
                #pragma unroll
                for (int u = 0; u < 4; u++) {
                    ulonglong2 a = *(const ulonglong2*)&As[(ttr + 8 * u) * 132 + kg * 4];
                    f2fma(ah[u], a.x, bh2.x); f2fma(ah[u], a.y, bh2.y);
                }
            }
        }

        #pragma unroll
        for (int u = 0; u < 4; u++) {
            const int m = m0 + ttr + 8 * u;
            const float ht = tanhf(ph[u] + f2sum(ah[u]));
            const float hn = fmaf(zloc[u], ht - hv[u], hv[u]);
            hnext[m * HID_ + j] = hn;
            hs_out[((size_t)m * T_ + t) * HID_ + j] = hn;
        }
        if (t < T_ - 1) gbar(base + (++nbar));
    }
}

// =====================================================================================
// Kernel 4: out = relu(h_last @ w_out + b_out).  M=256, N=256, K=512.
// =====================================================================================
__global__ __launch_bounds__(256) void out_kernel(
    const float* __restrict__ w_out, const float* __restrict__ b_out,
    float* __restrict__ out)
{
    __shared__ __align__(16) float As[32][36];
    __shared__ __align__(16) float Bs[32][36];

    const float* __restrict__ hlast = g_h[0];   // T even -> final state in buffer 0

    const int tid = threadIdx.x;
    const int m0 = blockIdx.y * 32;
    const int n0 = blockIdx.x * 32;

    const int ttr = tid >> 4;
    const int ttc = tid & 15;
    const int arow = tid >> 3;
    const int akq  = tid & 7;
    const int bkr  = tid >> 3;
    const int bnq  = tid & 7;

    u64 acc[2][2];
    #pragma unroll
    for (int i = 0; i < 2; i++)
        #pragma unroll
        for (int p = 0; p < 2; p++) acc[i][p] = 0ull;

    for (int k0 = 0; k0 < HID_; k0 += 32) {
        float4 av = *(const float4*)&hlast[(size_t)(m0 + arow) * HID_ + k0 + akq * 4];
        float4 bv = *(const float4*)&w_out[(size_t)(k0 + bkr) * OUT_ + n0 + bnq * 4];

        __syncthreads();
        *(float4*)&As[arow][akq * 4] = av;
        Bs[bnq * 4 + 0][bkr] = bv.x; Bs[bnq * 4 + 1][bkr] = bv.y;
        Bs[bnq * 4 + 2][bkr] = bv.z; Bs[bnq * 4 + 3][bkr] = bv.w;
        __syncthreads();

        #pragma unroll
        for (int q = 0; q < 8; q++) {
            ulonglong2 a0 = *(const ulonglong2*)&As[ttr * 2 + 0][q * 4];
            ulonglong2 a1 = *(const ulonglong2*)&As[ttr * 2 + 1][q * 4];
            #pragma unroll
            for (int p = 0; p < 2; p++) {
                ulonglong2 bb = *(const ulonglong2*)&Bs[ttc + 16 * p][q * 4];
                f2fma(acc[0][p], a0.x, bb.x); f2fma(acc[0][p], a0.y, bb.y);
                f2fma(acc[1][p], a1.x, bb.x); f2fma(acc[1][p], a1.y, bb.y);
            }
        }
    }

    #pragma unroll
    for (int i = 0; i < 2; i++) {
        const int b = m0 + ttr * 2 + i;
        #pragma unroll
        for (int p = 0; p < 2; p++) {
            const int j = n0 + ttc + 16 * p;
            const float s = f2sum(acc[i][p]) + b_out[j];
            out[(size_t)b * OUT_ + j] = fmaxf(s, 0.0f);
        }
    }
}

// =====================================================================================
extern "C" void kernel_launch(void* const* d_in, const int* in_sizes, int n_in,
                              void* d_out, int out_size)
{
    const float* x     = (const float*)d_in[0];
    const float* c     = (const float*)d_in[1];
    const float* h0    = (const float*)d_in[2];
    const float* w_hr  = (const float*)d_in[4];
    const float* w_xz  = (const float*)d_in[6];
    const float* w_hz  = (const float*)d_in[7];
    const float* w_cz  = (const float*)d_in[8];
    const float* w_xh  = (const float*)d_in[9];
    const float* w_hh  = (const float*)d_in[10];
    const float* w_ch  = (const float*)d_in[11];
    const float* w_xr  = (const float*)d_in[3];
    const float* w_cr  = (const float*)d_in[5];
    const float* b_r   = (const float*)d_in[12];
    const float* b_z   = (const float*)d_in[13];
    const float* b_h   = (const float*)d_in[14];
    const float* w_out = (const float*)d_in[15];
    const float* b_out = (const float*)d_in[16];

    float* out = (float*)d_out;                 // [B, OUT] first
    float* hs  = out + (size_t)B_ * OUT_;       // then [B, T, HID]

    static int smem_set = 0;
    if (!smem_set) {
        cudaFuncSetAttribute(scan_kernel, cudaFuncAttributeMaxDynamicSharedMemorySize,
                             (int)SCAN_SMEM);
        smem_set = 1;
    }

    cudaMemcpyToSymbolAsync(g_h, h0, (size_t)B_ * HID_ * sizeof(float), 0,
                            cudaMemcpyDeviceToDevice, 0);

    pre_gemm_kernel<<<dim3(24, 1024), 256>>>(x, c,
                                             w_xz, w_cz, b_z,
                                             w_xr, w_cr, b_r,
                                             w_xh, w_ch, b_h);

    scan_kernel<<<NBLK, 256, SCAN_SMEM>>>(w_hz, w_hr, w_hh, hs);

    out_kernel<<<dim3(8, 8), 256>>>(w_out, b_out, out);
}

// round 5
// speedup vs baseline: 1.6221x; 1.0054x over previous
#include <cuda_runtime.h>
#include <math.h>

#define B_   256
#define T_   256
#define IN_  256
#define HID_ 512
#define OUT_ 256
#define NBLK 128

typedef unsigned long long u64;

// ---------- packed f32x2 FMA (K packed into the two halves) ----------
__device__ __forceinline__ void f2fma(u64 &d, u64 a, u64 b) {
    asm("fma.rn.f32x2 %0, %1, %2, %0;" : "+l"(d) : "l"(a), "l"(b));
}
__device__ __forceinline__ float f2sum(u64 v) {
    unsigned lo, hi;
    asm("mov.b64 {%0, %1}, %2;" : "=r"(lo), "=r"(hi) : "l"(v));
    return __uint_as_float(lo) + __uint_as_float(hi);
}
__device__ __forceinline__ float sigmoidf_(float x) { return 1.0f / (1.0f + expf(-x)); }

// ---------- device scratch ----------
__device__ float g_pre[(size_t)B_ * T_ * 3 * HID_];   // [m][z|r|h], bias folded
__device__ float g_h[2][B_ * HID_];
__device__ float g_rh[B_ * HID_];
__device__ unsigned g_flags[NBLK * 32];               // 128B-spaced flags, zero-init, monotonic

// =====================================================================================
// Kernel 1: PRE = [x|c] @ [W_x;W_c](gate) + bias.  M=65536, N=1536, K=512.
// Tile 64x64, 256 threads, 4x4 f32x2 thread tile. Register-prefetched chunks,
// XOR-swizzled B smem store (conflict-free).
// =====================================================================================
__global__ __launch_bounds__(256) void pre_gemm_kernel(
    const float* __restrict__ x, const float* __restrict__ c,
    const float* __restrict__ wxz, const float* __restrict__ wcz, const float* __restrict__ bz,
    const float* __restrict__ wxr, const float* __restrict__ wcr, const float* __restrict__ br,
    const float* __restrict__ wxh, const float* __restrict__ wch, const float* __restrict__ bh)
{
    __shared__ __align__(16) float As[64][36];
    __shared__ __align__(16) float Bs[64 * 36];      // [col][k], k-groups XOR-swizzled by col>>3

    const int tid = threadIdx.x;
    const int m0 = blockIdx.y * 64;
    const int n0 = blockIdx.x * 64;
    const int gate = n0 >> 9;
    const int nl0 = n0 & (HID_ - 1);

    const float* Wx   = (gate == 0) ? wxz : (gate == 1) ? wxr : wxh;
    const float* Wc   = (gate == 0) ? wcz : (gate == 1) ? wcr : wch;
    const float* bias = (gate == 0) ? bz  : (gate == 1) ? br  : bh;

    const int ttr = tid >> 4;        // 0..15
    const int ttc = tid & 15;        // 0..15
    const int arow = tid >> 2;       // 0..63
    const int akq  = tid & 3;        // 0..3
    const int bkr  = tid >> 3;       // 0..31 (k row within chunk)
    const int bnq  = tid & 7;        // 0..7  (8-col group)

    u64 acc[4][4];
    #pragma unroll
    for (int i = 0; i < 4; i++)
        #pragma unroll
        for (int p = 0; p < 4; p++) acc[i][p] = 0ull;

    // prologue: chunk 0 into registers
    float4 av0 = *(const float4*)&x[(size_t)(m0 + arow) * IN_ + akq * 4];
    float4 av1 = *(const float4*)&x[(size_t)(m0 + arow) * IN_ + 16 + akq * 4];
    float4 bv0 = *(const float4*)&Wx[(size_t)bkr * HID_ + nl0 + bnq * 8];
    float4 bv1 = *(const float4*)&Wx[(size_t)bkr * HID_ + nl0 + bnq * 8 + 4];

    const int bg = bkr >> 2;         // k-group 0..7
    const int bw = bkr & 3;          // k within group
    const int bsw = ((bg ^ bnq) << 2) + bw;   // swizzled offset within row

    for (int k0 = 0; k0 < 512; k0 += 32) {
        __syncthreads();
        *(float4*)&As[arow][akq * 4]      = av0;
        *(float4*)&As[arow][16 + akq * 4] = av1;
        {
            float tmp[8] = {bv0.x, bv0.y, bv0.z, bv0.w, bv1.x, bv1.y, bv1.z, bv1.w};
            #pragma unroll
            for (int c2 = 0; c2 < 8; c2++)
                Bs[(bnq * 8 + c2) * 36 + bsw] = tmp[c2];
        }
        __syncthreads();

        if (k0 + 32 < 512) {
            const int kn = k0 + 32;
            const float* Asrc = (kn < 256) ? x  : c;
            const float* Bsrc = (kn < 256) ? Wx : Wc;
            const int kb = kn & 255;
            av0 = *(const float4*)&Asrc[(size_t)(m0 + arow) * IN_ + kb + akq * 4];
            av1 = *(const float4*)&Asrc[(size_t)(m0 + arow) * IN_ + kb + 16 + akq * 4];
            bv0 = *(const float4*)&Bsrc[(size_t)(kb + bkr) * HID_ + nl0 + bnq * 8];
            bv1 = *(const float4*)&Bsrc[(size_t)(kb + bkr) * HID_ + nl0 + bnq * 8 + 4];
        }

        #pragma unroll
        for (int q = 0; q < 8; q++) {
            ulonglong2 a[4];
            #pragma unroll
            for (int i = 0; i < 4; i++)
                a[i] = *(const ulonglong2*)&As[ttr * 4 + i][q * 4];
            #pragma unroll
            for (int p = 0; p < 4; p++) {
                const int colp = ttc + 16 * p;
                ulonglong2 b = *(const ulonglong2*)&Bs[colp * 36 + ((q ^ (colp >> 3)) << 2)];
                #pragma unroll
                for (int i = 0; i < 4; i++) {
                    f2fma(acc[i][p], a[i].x, b.x);
                    f2fma(acc[i][p], a[i].y, b.y);
                }
            }
        }
    }

    #pragma unroll
    for (int i = 0; i < 4; i++) {
        const int m = m0 + ttr * 4 + i;
        #pragma unroll
        for (int p = 0; p < 4; p++) {
            const int cl = ttc + 16 * p;
            const int j  = nl0 + cl;
            g_pre[(size_t)m * 1536 + n0 + cl] = f2sum(acc[i][p]) + bias[j];
        }
    }
}

// =====================================================================================
// Flag-based grid barrier: one 128B-spaced flag per block, release/acquire, no atomics.
// =====================================================================================
__device__ __forceinline__ void gbar(unsigned want)
{
    __syncthreads();
    if (threadIdx.x == 0) {
        asm volatile("st.release.gpu.global.u32 [%0], %1;"
                     :: "l"(&g_flags[blockIdx.x * 32]), "r"(want) : "memory");
    }
    if (threadIdx.x < NBLK) {
        unsigned v;
        do {
            asm volatile("ld.acquire.gpu.global.u32 %0, [%1];"
                         : "=r"(v) : "l"(&g_flags[threadIdx.x * 32]) : "memory");
        } while ((int)(v - want) < 0);
    }
    __syncthreads();
}

// =====================================================================================
// Persistent scan kernel: 128 blocks = 8 m-tiles (32 rows) x 16 col-tiles (32 cols).
// Block computes BOTH z and r for its 32 cols (z kept in regs), then h-candidate.
// Weights in smem for all 256 steps; staged h/rh chunks software-pipelined.
// =====================================================================================
#define SC_WZR_F (64 * 516)
#define SC_WH_F  (32 * 516)
#define SC_AS_F  (32 * 132)
#define SCAN_SMEM ((SC_WZR_F + SC_WH_F + SC_AS_F) * sizeof(float))

__global__ __launch_bounds__(256, 1) void scan_kernel(
    const float* __restrict__ w_hz, const float* __restrict__ w_hr,
    const float* __restrict__ w_hh, float* __restrict__ hs_out)
{
    extern __shared__ float sm[];
    float* wZR = sm;                         // [64][516]: cols 0-31 = Whz slice, 32-63 = Whr slice
    float* wH  = sm + SC_WZR_F;              // [32][516]: Whh slice
    float* As  = sm + SC_WZR_F + SC_WH_F;    // [32][132] staging

    const int tid = threadIdx.x;
    const int bid = blockIdx.x;
    const int bm = bid >> 4;                 // 0..7
    const int bn = bid & 15;                 // 0..15
    const int m0 = bm * 32;
    const int j0 = bn * 32;

    // ---- one-time weight load (transposed to [col][k]) ----
    for (int idx = tid; idx < 512 * 8; idx += 256) {
        const int k  = idx >> 3;
        const int c4 = (idx & 7) * 4;
        float4 vz = *(const float4*)&w_hz[(size_t)k * HID_ + j0 + c4];
        float4 vr = *(const float4*)&w_hr[(size_t)k * HID_ + j0 + c4];
        float4 vh = *(const float4*)&w_hh[(size_t)k * HID_ + j0 + c4];
        wZR[(c4 + 0) * 516 + k] = vz.x; wZR[(c4 + 1) * 516 + k] = vz.y;
        wZR[(c4 + 2) * 516 + k] = vz.z; wZR[(c4 + 3) * 516 + k] = vz.w;
        wZR[(32 + c4 + 0) * 516 + k] = vr.x; wZR[(32 + c4 + 1) * 516 + k] = vr.y;
        wZR[(32 + c4 + 2) * 516 + k] = vr.z; wZR[(32 + c4 + 3) * 516 + k] = vr.w;
        wH[(c4 + 0) * 516 + k] = vh.x; wH[(c4 + 1) * 516 + k] = vh.y;
        wH[(c4 + 2) * 516 + k] = vh.z; wH[(c4 + 3) * 516 + k] = vh.w;
    }

    __shared__ unsigned s_base;
    if (tid == 0) s_base = *(volatile unsigned*)&g_flags[bid * 32];
    __syncthreads();
    const unsigned base = s_base;
    unsigned nbar = 0;

    // compute mapping: warp = 4 rows x 8 cols; block rows = ttr + 8u (u=0..3)
    const int wid  = tid >> 5, lane = tid & 31;
    const int ttr  = (wid >> 2) * 4 + (lane >> 3);   // 0..7
    const int col  = (wid & 3) * 8 + (lane & 7);     // 0..31
    const int j    = j0 + col;

    // staging mapping: 32 rows x 32 floats per chunk-quarter; XOR lane->granule for
    // conflict-free STS (slot = srow + g16 distinct within each srow group)
    const int srow = tid >> 3;
    const int sk   = (((tid & 7) ^ (srow & 7)) * 4);

    for (int t = 0; t < T_; t++) {
        const float* __restrict__ hprev = g_h[t & 1];
        float* __restrict__ hnext = g_h[(t + 1) & 1];

        // ---- epilogue prefetch (pre is static; hprev valid after prior barrier) ----
        float pz[4], pr[4], ph[4], hv[4];
        #pragma unroll
        for (int u = 0; u < 4; u++) {
            const int m = m0 + ttr + 8 * u;
            const size_t prow = ((size_t)m * T_ + t) * 1536;
            pz[u] = __ldg(&g_pre[prow + j]);
            pr[u] = __ldg(&g_pre[prow + 512 + j]);
            ph[u] = __ldg(&g_pre[prow + 1024 + j]);
            hv[u] = __ldcg(&hprev[m * HID_ + j]);
        }

        // ================= phase A: Sz,Sr = h @ [Whz|Whr] slice =================
        u64 az[4], ar[4];
        #pragma unroll
        for (int u = 0; u < 4; u++) { az[u] = 0ull; ar[u] = 0ull; }

        float4 r4[4];
        #pragma unroll
        for (int ps = 0; ps < 4; ps++)
            r4[ps] = __ldcg((const float4*)&hprev[(size_t)(m0 + srow) * HID_ + ps * 32 + sk]);

        for (int ch = 0; ch < 4; ch++) {
            const int k0 = ch * 128;
            __syncthreads();
            #pragma unroll
            for (int ps = 0; ps < 4; ps++)
                *(float4*)&As[srow * 132 + ps * 32 + sk] = r4[ps];
            __syncthreads();
            if (ch < 3) {
                #pragma unroll
                for (int ps = 0; ps < 4; ps++)
                    r4[ps] = __ldcg((const float4*)&hprev[(size_t)(m0 + srow) * HID_ + k0 + 128 + ps * 32 + sk]);
            }
            #pragma unroll 8
            for (int kg = 0; kg < 32; kg++) {
                ulonglong2 bz = *(const ulonglong2*)&wZR[col * 516 + k0 + kg * 4];
                ulonglong2 br2 = *(const ulonglong2*)&wZR[(col + 32) * 516 + k0 + kg * 4];
                #pragma unroll
                for (int u = 0; u < 4; u++) {
                    ulonglong2 a = *(const ulonglong2*)&As[(ttr + 8 * u) * 132 + kg * 4];
                    f2fma(az[u], a.x, bz.x); f2fma(az[u], a.y, bz.y);
                    f2fma(ar[u], a.x, br2.x); f2fma(ar[u], a.y, br2.y);
                }
            }
        }

        float zloc[4];
        #pragma unroll
        for (int u = 0; u < 4; u++) {
            const int m = m0 + ttr + 8 * u;
            zloc[u] = sigmoidf_(pz[u] + f2sum(az[u]));
            const float r = sigmoidf_(pr[u] + f2sum(ar[u]));
            g_rh[m * HID_ + j] = r * hv[u];
        }
        gbar(base + (++nbar));

        // ================= phase B: Sh = rh @ Whh slice =================
        u64 ah[4];
        #pragma unroll
        for (int u = 0; u < 4; u++) ah[u] = 0ull;

        #pragma unroll
        for (int ps = 0; ps < 4; ps++)
            r4[ps] = __ldcg((const float4*)&g_rh[(size_t)(m0 + srow) * HID_ + ps * 32 + sk]);

        for (int ch = 0; ch < 4; ch++) {
            const int k0 = ch * 128;
            __syncthreads();
            #pragma unroll
            for (int ps = 0; ps < 4; ps++)
                *(float4*)&As[srow * 132 + ps * 32 + sk] = r4[ps];
            __syncthreads();
            if (ch < 3) {
                #pragma unroll
                for (int ps = 0; ps < 4; ps++)
                    r4[ps] = __ldcg((const float4*)&g_rh[(size_t)(m0 + srow) * HID_ + k0 + 128 + ps * 32 + sk]);
            }
            #pragma unroll 8
            for (int kg = 0; kg < 32; kg++) {
                ulonglong2 bh2 = *(const ulonglong2*)&wH[col * 516 + k0 + kg * 4];
                #pragma unroll
                for (int u = 0; u < 4; u++) {
                    ulonglong2 a = *(const ulonglong2*)&As[(ttr + 8 * u) * 132 + kg * 4];
                    f2fma(ah[u], a.x, bh2.x); f2fma(ah[u], a.y, bh2.y);
                }
            }
        }

        #pragma unroll
        for (int u = 0; u < 4; u++) {
            const int m = m0 + ttr + 8 * u;
            const float ht = tanhf(ph[u] + f2sum(ah[u]));
            const float hn = fmaf(zloc[u], ht - hv[u], hv[u]);
            hnext[m * HID_ + j] = hn;
            hs_out[((size_t)m * T_ + t) * HID_ + j] = hn;
        }
        if (t < T_ - 1) gbar(base + (++nbar));
    }
}

// =====================================================================================
// Kernel 4: out = relu(h_last @ w_out + b_out).  M=256, N=256, K=512.
// =====================================================================================
__global__ __launch_bounds__(256) void out_kernel(
    const float* __restrict__ w_out, const float* __restrict__ b_out,
    float* __restrict__ out)
{
    __shared__ __align__(16) float As[32][36];
    __shared__ __align__(16) float Bs[32][36];

    const float* __restrict__ hlast = g_h[0];   // T even -> final state in buffer 0

    const int tid = threadIdx.x;
    const int m0 = blockIdx.y * 32;
    const int n0 = blockIdx.x * 32;

    const int ttr = tid >> 4;
    const int ttc = tid & 15;
    const int arow = tid >> 3;
    const int akq  = tid & 7;
    const int bkr  = tid >> 3;
    const int bnq  = tid & 7;

    u64 acc[2][2];
    #pragma unroll
    for (int i = 0; i < 2; i++)
        #pragma unroll
        for (int p = 0; p < 2; p++) acc[i][p] = 0ull;

    for (int k0 = 0; k0 < HID_; k0 += 32) {
        float4 av = *(const float4*)&hlast[(size_t)(m0 + arow) * HID_ + k0 + akq * 4];
        float4 bv = *(const float4*)&w_out[(size_t)(k0 + bkr) * OUT_ + n0 + bnq * 4];

        __syncthreads();
        *(float4*)&As[arow][akq * 4] = av;
        Bs[bnq * 4 + 0][bkr] = bv.x; Bs[bnq * 4 + 1][bkr] = bv.y;
        Bs[bnq * 4 + 2][bkr] = bv.z; Bs[bnq * 4 + 3][bkr] = bv.w;
        __syncthreads();

        #pragma unroll
        for (int q = 0; q < 8; q++) {
            ulonglong2 a0 = *(const ulonglong2*)&As[ttr * 2 + 0][q * 4];
            ulonglong2 a1 = *(const ulonglong2*)&As[ttr * 2 + 1][q * 4];
            #pragma unroll
            for (int p = 0; p < 2; p++) {
                ulonglong2 bb = *(const ulonglong2*)&Bs[ttc + 16 * p][q * 4];
                f2fma(acc[0][p], a0.x, bb.x); f2fma(acc[0][p], a0.y, bb.y);
                f2fma(acc[1][p], a1.x, bb.x); f2fma(acc[1][p], a1.y, bb.y);
            }
        }
    }

    #pragma unroll
    for (int i = 0; i < 2; i++) {
        const int b = m0 + ttr * 2 + i;
        #pragma unroll
        for (int p = 0; p < 2; p++) {
            const int j = n0 + ttc + 16 * p;
            const float s = f2sum(acc[i][p]) + b_out[j];
            out[(size_t)b * OUT_ + j] = fmaxf(s, 0.0f);
        }
    }
}

// =====================================================================================
extern "C" void kernel_launch(void* const* d_in, const int* in_sizes, int n_in,
                              void* d_out, int out_size)
{
    const float* x     = (const float*)d_in[0];
    const float* c     = (const float*)d_in[1];
    const float* h0    = (const float*)d_in[2];
    const float* w_hr  = (const float*)d_in[4];
    const float* w_xz  = (const float*)d_in[6];
    const float* w_hz  = (const float*)d_in[7];
    const float* w_cz  = (const float*)d_in[8];
    const float* w_xh  = (const float*)d_in[9];
    const float* w_hh  = (const float*)d_in[10];
    const float* w_ch  = (const float*)d_in[11];
    const float* w_xr  = (const float*)d_in[3];
    const float* w_cr  = (const float*)d_in[5];
    const float* b_r   = (const float*)d_in[12];
    const float* b_z   = (const float*)d_in[13];
    const float* b_h   = (const float*)d_in[14];
    const float* w_out = (const float*)d_in[15];
    const float* b_out = (const float*)d_in[16];

    float* out = (float*)d_out;                 // [B, OUT] first
    float* hs  = out + (size_t)B_ * OUT_;       // then [B, T, HID]

    static int smem_set = 0;
    if (!smem_set) {
        cudaFuncSetAttribute(scan_kernel, cudaFuncAttributeMaxDynamicSharedMemorySize,
                             (int)SCAN_SMEM);
        smem_set = 1;
    }

    cudaMemcpyToSymbolAsync(g_h, h0, (size_t)B_ * HID_ * sizeof(float), 0,
                            cudaMemcpyDeviceToDevice, 0);

    pre_gemm_kernel<<<dim3(24, 1024), 256>>>(x, c,
                                             w_xz, w_cz, b_z,
                                             w_xr, w_cr, b_r,
                                             w_xh, w_ch, b_h);

    scan_kernel<<<NBLK, 256, SCAN_SMEM>>>(w_hz, w_hr, w_hh, hs);

    out_kernel<<<dim3(8, 8), 256>>>(w_out, b_out, out);
}